// round 1
// baseline (speedup 1.0000x reference)
#include <cuda_runtime.h>
#include <math.h>

// Problem shapes (fixed by setup_inputs)
#define B_    1
#define N_    4096
#define V_    2
#define W_    32
#define H_    16
#define M_    512          // W_*H_
#define EPSF  1e-6f
#define PIF   3.14159265358979323846f

// inputs (metadata order):
// 0 points_normals   (B,N,3)
// 1 points_albedo    (B,N,3)
// 2 points_metallic  (B,N,1)
// 3 points_smoothness(B,N,1)
// 4 viewing_dirs     (B,N,V,3)
// 5 env_vis          (B,N,M)
// 6 env_map          (B,W,H,3)
// output: (B,N,V,3)

__global__ __launch_bounds__(256) void hdr_render_kernel(
    const float* __restrict__ normals,
    const float* __restrict__ albedo,
    const float* __restrict__ metallic,
    const float* __restrict__ smoothness,
    const float* __restrict__ viewdirs,
    const float* __restrict__ env_vis,
    const float* __restrict__ env_map,
    float* __restrict__ out)
{
    // Per-m tables, identical across all pairs. SoA as float4 for LDS.128.
    __shared__ float4 s_dir_sa[M_];  // (lx, ly, lz, sa)
    __shared__ float4 s_li[M_];      // (LiR, LiG, LiB, 0)

    const int tid = threadIdx.x;

    for (int m = tid; m < M_; m += blockDim.x) {
        const int j = m >> 5;          // m / W_ (W_=32)
        const int i = m & (W_ - 1);    // m % W_
        const float u  = ((float)i + 0.5f) * (1.0f / (float)W_);
        const float vv = ((float)j + 0.5f) * (1.0f / (float)H_);
        const float phi   = u * (2.0f * PIF) + 0.5f * PIF;
        const float theta = vv * PIF;
        float st, ct, sp, cp;
        sincosf(theta, &st, &ct);
        sincosf(phi,   &sp, &cp);
        const float sa = st * (PIF / (float)H_) * (2.0f * PIF / (float)W_);
        s_dir_sa[m] = make_float4(st * cp, ct, -st * sp, sa);
        // bilinear grid_sample degenerates to exact texel fetch: Li = env_map[0, i, j, :]
        const float* e = env_map + (i * H_ + j) * 3;
        s_li[m] = make_float4(e[0], e[1], e[2], 0.0f);
    }
    __syncthreads();

    const int gwarp = (blockIdx.x * blockDim.x + tid) >> 5;  // pair index = n*V + vi
    const int lane  = tid & 31;
    if (gwarp >= N_ * V_) return;
    const int n  = gwarp >> 1;   // V_=2
    const int vi = gwarp & 1;

    // ---- per-pair (warp-invariant) setup ----
    float nx = normals[n * 3 + 0];
    float ny = normals[n * 3 + 1];
    float nz = normals[n * 3 + 2];
    {
        const float inv = rsqrtf(fmaxf(nx * nx + ny * ny + nz * nz, 1e-24f));
        nx *= inv; ny *= inv; nz *= inv;
    }
    const float* vd = viewdirs + (n * V_ + vi) * 3;
    float vx = vd[0], vy = vd[1], vz = vd[2];
    {
        const float inv = rsqrtf(fmaxf(vx * vx + vy * vy + vz * vz, 1e-24f));
        vx *= inv; vy *= inv; vz *= inv;
    }

    const float met    = metallic[n];
    const float rough  = 1.0f - smoothness[n];
    const float alpha  = rough * rough;
    const float alpha2 = alpha * alpha;
    const float a2m1   = alpha2 - 1.0f;
    const float k      = 0.5f * alpha;
    const float omk    = 1.0f - k;

    const float ar = albedo[n * 3 + 0];
    const float ag = albedo[n * 3 + 1];
    const float ab = albedo[n * 3 + 2];
    const float f0r = 0.04f + (ar - 0.04f) * met;
    const float f0g = 0.04f + (ag - 0.04f) * met;
    const float f0b = 0.04f + (ab - 0.04f) * met;
    const float omf0r = 1.0f - f0r;
    const float omf0g = 1.0f - f0g;
    const float omf0b = 1.0f - f0b;

    const float NdotV = fmaxf(nx * vx + ny * vy + nz * vz, EPSF);
    const float Gv    = NdotV / (NdotV * omk + k + EPSF);
    const float a2Gv  = alpha2 * Gv;

    const float dcom = (1.0f - met) * (1.0f / PIF);
    const float dR = dcom * ar;
    const float dG = dcom * ag;
    const float dB = dcom * ab;

    const float* __restrict__ vis = env_vis + n * M_;

    float accR = 0.0f, accG = 0.0f, accB = 0.0f;

    #pragma unroll 4
    for (int m = lane; m < M_; m += 32) {
        const float4 ds = s_dir_sa[m];
        const float lx = ds.x, ly = ds.y, lz = ds.z, sa = ds.w;

        const float hx = vx + lx, hy = vy + ly, hz = vz + lz;
        const float hinv = rsqrtf(fmaxf(hx * hx + hy * hy + hz * hz, 1e-24f));

        const float NdotL = fmaxf(nx * lx + ny * ly + nz * lz, EPSF);
        const float NdotH = fmaxf((nx * hx + ny * hy + nz * hz) * hinv, 0.0f);
        const float VdotH = fmaxf((lx * hx + ly * hy + lz * hz) * hinv, 0.0f);

        // Fresnel power term: (1 - clamp(VdotH,0,1))^5
        const float t  = 1.0f - fminf(VdotH, 1.0f);
        const float t2 = t * t;
        const float p5 = t2 * t2 * t;

        // GGX D, Smith G, combined with single fast division:
        // spec_scalar s = alpha2*Gv*NdotL / ((pi*d^2+EPS)*(NdotL*(1-k)+k+EPS)*(4*NdotV*NdotL+EPS))
        const float dd   = fmaf(NdotH * NdotH, a2m1, 1.0f);
        const float den1 = fmaf(PIF * dd, dd, EPSF);
        const float den2 = fmaf(NdotL, omk, k) + EPSF;
        const float den3 = fmaf(4.0f * NdotV, NdotL, EPSF);
        const float s    = __fdividef(a2Gv * NdotL, den1 * den2 * den3);

        const float4 li = s_li[m];
        const float w = vis[m] * NdotL * sa;

        // brdf = diffuseBase*(1-Fr) + Fr*s = dX + Fr*(s - dX)
        const float FrR = fmaf(omf0r, p5, f0r);
        const float FrG = fmaf(omf0g, p5, f0g);
        const float FrB = fmaf(omf0b, p5, f0b);

        const float brdfR = fmaf(FrR, s - dR, dR);
        const float brdfG = fmaf(FrG, s - dG, dG);
        const float brdfB = fmaf(FrB, s - dB, dB);

        accR = fmaf(brdfR * li.x, w, accR);
        accG = fmaf(brdfG * li.y, w, accG);
        accB = fmaf(brdfB * li.z, w, accB);
    }

    // warp tree-reduction of 3 channels
    #pragma unroll
    for (int off = 16; off > 0; off >>= 1) {
        accR += __shfl_down_sync(0xffffffffu, accR, off);
        accG += __shfl_down_sync(0xffffffffu, accG, off);
        accB += __shfl_down_sync(0xffffffffu, accB, off);
    }

    if (lane == 0) {
        float* o = out + gwarp * 3;
        o[0] = accR;
        o[1] = accG;
        o[2] = accB;
    }
}

extern "C" void kernel_launch(void* const* d_in, const int* in_sizes, int n_in,
                              void* d_out, int out_size)
{
    const float* normals    = (const float*)d_in[0];
    const float* albedo     = (const float*)d_in[1];
    const float* metallic   = (const float*)d_in[2];
    const float* smoothness = (const float*)d_in[3];
    const float* viewdirs   = (const float*)d_in[4];
    const float* env_vis    = (const float*)d_in[5];
    const float* env_map    = (const float*)d_in[6];
    float* out = (float*)d_out;

    // one warp per (n, v) pair
    const int pairs   = N_ * V_;            // 8192
    const int threads = 256;                 // 8 warps/block
    const int blocks  = (pairs * 32 + threads - 1) / threads;  // 1024

    hdr_render_kernel<<<blocks, threads>>>(normals, albedo, metallic, smoothness,
                                           viewdirs, env_vis, env_map, out);
}